// round 5
// baseline (speedup 1.0000x reference)
#include <cuda_runtime.h>
#include <math.h>
#include <stdint.h>

#define BB 8
#define TT 4096
#define NM 1024
#define DD 128

// Scratch: k_rot (acts as Q and K) and v (= k pre-RoPE)
__device__ float g_k[BB * TT * DD];
__device__ float g_v[BB * TT * DD];

__device__ __forceinline__ uint32_t f2tf(float x) {
    uint32_t r;
    asm("cvt.rna.tf32.f32 %0, %1;" : "=r"(r) : "f"(x));
    return r;
}

__device__ __forceinline__ void mma_tf32(float* c, const uint32_t* a,
                                         uint32_t b0, uint32_t b1) {
    asm volatile(
        "mma.sync.aligned.m16n8k8.row.col.f32.tf32.tf32.f32 "
        "{%0,%1,%2,%3}, {%4,%5,%6,%7}, {%8,%9}, {%0,%1,%2,%3};\n"
        : "+f"(c[0]), "+f"(c[1]), "+f"(c[2]), "+f"(c[3])
        : "r"(a[0]), "r"(a[1]), "r"(a[2]), "r"(a[3]), "r"(b0), "r"(b1));
}

// ---------------------------------------------------------------------------
// Kernel 1: k = x @ W_K^T via tf32 mma (2-pass split on x, W tf32-rounded),
// RoPE fused in the epilogue (C-fragment cols 2t,2t+1 are the RoPE pair).
// ---------------------------------------------------------------------------
__global__ __launch_bounds__(128) void proj_rope_kernel(
    const float* __restrict__ x, const float* __restrict__ W) {
    __shared__ float sX[64 * 36];
    __shared__ uint32_t sWu[128 * 36];

    const int tid = threadIdx.x;
    const int w = tid >> 5;
    const int lane = tid & 31;
    const int g = lane >> 2;
    const int t = lane & 3;
    const int mBase = w * 16;
    const int m0 = blockIdx.x * 64;

    float c[16][4];
#pragma unroll
    for (int nt = 0; nt < 16; nt++)
#pragma unroll
        for (int e = 0; e < 4; e++) c[nt][e] = 0.f;

    for (int kc = 0; kc < NM; kc += 32) {
        __syncthreads();
#pragma unroll
        for (int p = 0; p < 4; p++) {
            int idx = tid + 128 * p;
            int row = idx >> 3;
            int c4 = (idx & 7) * 4;
            *(float4*)&sX[row * 36 + c4] =
                *(const float4*)&x[(size_t)(m0 + row) * NM + kc + c4];
        }
#pragma unroll
        for (int p = 0; p < 8; p++) {
            int idx = tid + 128 * p;
            int row = idx >> 3;
            int c4 = (idx & 7) * 4;
            float4 wv = *(const float4*)&W[(size_t)row * NM + kc + c4];
            uint4 wu = make_uint4(f2tf(wv.x), f2tf(wv.y), f2tf(wv.z), f2tf(wv.w));
            *(uint4*)&sWu[row * 36 + c4] = wu;
        }
        __syncthreads();

#pragma unroll
        for (int kt = 0; kt < 4; kt++) {
            const int k0 = kt * 8;
            float a0 = sX[(mBase + g) * 36 + k0 + t];
            float a1 = sX[(mBase + g + 8) * 36 + k0 + t];
            float a2 = sX[(mBase + g) * 36 + k0 + t + 4];
            float a3 = sX[(mBase + g + 8) * 36 + k0 + t + 4];
            uint32_t ahi[4], alo[4];
            ahi[0] = f2tf(a0); ahi[1] = f2tf(a1);
            ahi[2] = f2tf(a2); ahi[3] = f2tf(a3);
            alo[0] = f2tf(a0 - __uint_as_float(ahi[0]));
            alo[1] = f2tf(a1 - __uint_as_float(ahi[1]));
            alo[2] = f2tf(a2 - __uint_as_float(ahi[2]));
            alo[3] = f2tf(a3 - __uint_as_float(ahi[3]));
#pragma unroll
            for (int nt = 0; nt < 16; nt++) {
                uint32_t b0 = sWu[(nt * 8 + g) * 36 + k0 + t];
                uint32_t b1 = sWu[(nt * 8 + g) * 36 + k0 + t + 4];
                mma_tf32(c[nt], ahi, b0, b1);
                mma_tf32(c[nt], alo, b0, b1);
            }
        }
    }

    const size_t row0 = (size_t)(m0 + mBase + g);
    const size_t row1 = row0 + 8;
#pragma unroll
    for (int nt = 0; nt < 16; nt++) {
        int col = nt * 8 + 2 * t;
        int h = col >> 1;
        float ang = powf(10000.0f, -(float)h * (1.0f / 64.0f));
        float cc = cosf(ang), ss = sinf(ang);
        float e0 = fmaf(c[nt][0], cc, c[nt][1] * ss);
        float o0 = fmaf(-e0, ss, c[nt][1] * cc);
        float e1 = fmaf(c[nt][2], cc, c[nt][3] * ss);
        float o1 = fmaf(-e1, ss, c[nt][3] * cc);
        *(float2*)&g_v[row0 * DD + col] = make_float2(c[nt][0], c[nt][1]);
        *(float2*)&g_v[row1 * DD + col] = make_float2(c[nt][2], c[nt][3]);
        *(float2*)&g_k[row0 * DD + col] = make_float2(e0, o0);
        *(float2*)&g_k[row1 * DD + col] = make_float2(e1, o1);
    }
}

// ---------------------------------------------------------------------------
// Kernel 2: causal flash attention, tf32 mma.
// BLOCK_M=128 (8 warps x 16 rows), BLOCK_N=64, 256 threads, 1 CTA/SM.
// Q stored pre-split (hi/lo tf32) in smem ONCE; mainloop A-path is pure LDS.
// S = QK^T uses 2-pass (hi+lo); P·V uses hi-only P (P in [0,1]).
// smem: sQhi[128][132] | sQlo[128][132] | sKu[64][132] | sVu[64][136]
//       | sP 8 x [16][12]  -> 209920 B, 1 CTA/SM.
// ---------------------------------------------------------------------------
#define QSTR 132
#define KSTR 132
#define VSTR 136
#define OFF_QLO (128 * QSTR)
#define OFF_K (OFF_QLO + 128 * QSTR)
#define OFF_V (OFF_K + 64 * KSTR)
#define OFF_P (OFF_V + 64 * VSTR)
#define ATT_SMEM ((OFF_P + 8 * 16 * 12) * 4)

__global__ __launch_bounds__(256, 1) void attn_kernel(float* __restrict__ out) {
    extern __shared__ uint32_t smu[];
    uint32_t* sQhi = smu;
    uint32_t* sQlo = smu + OFF_QLO;
    uint32_t* sKu = smu + OFF_K;
    uint32_t* sVu = smu + OFF_V;
    float* sP = (float*)(smu + OFF_P);

    const int tid = threadIdx.x;
    const int w = tid >> 5;
    const int lane = tid & 31;
    const int g = lane >> 2;
    const int t = lane & 3;
    const int mBase = w * 16;

    const int b = blockIdx.x;
    const int i_tile = 31 - (int)blockIdx.y;  // heavy tiles in wave 1
    const int q0 = i_tile * 128;

    const float* __restrict__ Kb = g_k + (size_t)b * TT * DD;
    const float* __restrict__ Vb = g_v + (size_t)b * TT * DD;
    float* sPw = sP + w * 16 * 12;

    const float SCALE = 0.08838834764831845f;  // 128^-0.5
    const float NEG_INF = __int_as_float(0xff800000);

    // ---- fill Q (pre-scaled, pre-split hi/lo tf32) ONCE ----
#pragma unroll
    for (int p = 0; p < 16; p++) {
        int idx = tid + 256 * p;          // 0..4095 float4 units
        int row = idx >> 5;
        int c4 = (idx & 31) * 4;
        float4 v = *(const float4*)&Kb[(size_t)(q0 + row) * DD + c4];
        v.x *= SCALE; v.y *= SCALE; v.z *= SCALE; v.w *= SCALE;
        uint4 hi = make_uint4(f2tf(v.x), f2tf(v.y), f2tf(v.z), f2tf(v.w));
        uint4 lo = make_uint4(f2tf(v.x - __uint_as_float(hi.x)),
                              f2tf(v.y - __uint_as_float(hi.y)),
                              f2tf(v.z - __uint_as_float(hi.z)),
                              f2tf(v.w - __uint_as_float(hi.w)));
        *(uint4*)&sQhi[row * QSTR + c4] = hi;
        *(uint4*)&sQlo[row * QSTR + c4] = lo;
    }

    float O[16][4];
    float m_i[2], l_i[2];
#pragma unroll
    for (int nt = 0; nt < 16; nt++)
#pragma unroll
        for (int e = 0; e < 4; e++) O[nt][e] = 0.f;
    m_i[0] = NEG_INF; m_i[1] = NEG_INF;
    l_i[0] = 0.f; l_i[1] = 0.f;

    const int jmax = 2 * i_tile + 1;
    for (int jt = 0; jt <= jmax; jt++) {
        const int j0 = jt * 64;
        __syncthreads();  // prior iter done with sK/sV; also orders Q fill

        // ---- fill K/V (tf32-rounded) ----
#pragma unroll
        for (int p = 0; p < 8; p++) {
            int idx = tid + 256 * p;      // 0..2047 float4 units
            int row = idx >> 5;
            int c4 = (idx & 31) * 4;
            float4 kv = *(const float4*)&Kb[(size_t)(j0 + row) * DD + c4];
            uint4 ku = make_uint4(f2tf(kv.x), f2tf(kv.y), f2tf(kv.z), f2tf(kv.w));
            *(uint4*)&sKu[row * KSTR + c4] = ku;
            float4 vv = *(const float4*)&Vb[(size_t)(j0 + row) * DD + c4];
            uint4 vu = make_uint4(f2tf(vv.x), f2tf(vv.y), f2tf(vv.z), f2tf(vv.w));
            *(uint4*)&sVu[row * VSTR + c4] = vu;
        }
        __syncthreads();

        // ---- S = Q K^T (2-pass) ----
        float c[8][4];
#pragma unroll
        for (int nt = 0; nt < 8; nt++)
#pragma unroll
            for (int e = 0; e < 4; e++) c[nt][e] = 0.f;

#pragma unroll 4
        for (int kt = 0; kt < 16; kt++) {
            const int k0 = kt * 8;
            uint32_t ahi[4], alo[4];
            ahi[0] = sQhi[(mBase + g) * QSTR + k0 + t];
            ahi[1] = sQhi[(mBase + g + 8) * QSTR + k0 + t];
            ahi[2] = sQhi[(mBase + g) * QSTR + k0 + t + 4];
            ahi[3] = sQhi[(mBase + g + 8) * QSTR + k0 + t + 4];
            alo[0] = sQlo[(mBase + g) * QSTR + k0 + t];
            alo[1] = sQlo[(mBase + g + 8) * QSTR + k0 + t];
            alo[2] = sQlo[(mBase + g) * QSTR + k0 + t + 4];
            alo[3] = sQlo[(mBase + g + 8) * QSTR + k0 + t + 4];
#pragma unroll
            for (int nt = 0; nt < 8; nt++) {
                uint32_t b0 = sKu[(nt * 8 + g) * KSTR + k0 + t];
                uint32_t b1 = sKu[(nt * 8 + g) * KSTR + k0 + t + 4];
                mma_tf32(c[nt], ahi, b0, b1);
                mma_tf32(c[nt], alo, b0, b1);
            }
        }

        // ---- causal mask (only the last two j-tiles intersect the diagonal) ----
        if (jt >= 2 * i_tile) {
            const int dj = j0 - q0;           // 0 or 64
            const int r0 = mBase + g;
            const int r1 = mBase + g + 8;
#pragma unroll
            for (int nt = 0; nt < 8; nt++) {
                int c0 = dj + nt * 8 + 2 * t;
                if (c0 > r0) c[nt][0] = NEG_INF;
                if (c0 + 1 > r0) c[nt][1] = NEG_INF;
                if (c0 > r1) c[nt][2] = NEG_INF;
                if (c0 + 1 > r1) c[nt][3] = NEG_INF;
            }
        }

        // ---- online softmax (rows g and g+8) ----
#pragma unroll
        for (int ri = 0; ri < 2; ri++) {
            float mx = NEG_INF;
#pragma unroll
            for (int nt = 0; nt < 8; nt++)
                mx = fmaxf(mx, fmaxf(c[nt][2 * ri], c[nt][2 * ri + 1]));
            mx = fmaxf(mx, __shfl_xor_sync(0xffffffffu, mx, 1));
            mx = fmaxf(mx, __shfl_xor_sync(0xffffffffu, mx, 2));
            float mnew = fmaxf(m_i[ri], mx);
            float sc = __expf(m_i[ri] - mnew);
            float rsum = 0.f;
#pragma unroll
            for (int nt = 0; nt < 8; nt++) {
                c[nt][2 * ri] = __expf(c[nt][2 * ri] - mnew);
                c[nt][2 * ri + 1] = __expf(c[nt][2 * ri + 1] - mnew);
                rsum += c[nt][2 * ri] + c[nt][2 * ri + 1];
            }
            rsum += __shfl_xor_sync(0xffffffffu, rsum, 1);
            rsum += __shfl_xor_sync(0xffffffffu, rsum, 2);
            l_i[ri] = l_i[ri] * sc + rsum;
            m_i[ri] = mnew;
#pragma unroll
            for (int nt = 0; nt < 16; nt++) {
                O[nt][2 * ri] *= sc;
                O[nt][2 * ri + 1] *= sc;
            }
        }

        // ---- O += P V (P hi-only; P in [0,1] so tf32 rounding is benign) ----
#pragma unroll
        for (int kt = 0; kt < 8; kt++) {
            *(float2*)&sPw[g * 12 + 2 * t] = make_float2(c[kt][0], c[kt][1]);
            *(float2*)&sPw[(g + 8) * 12 + 2 * t] = make_float2(c[kt][2], c[kt][3]);
            __syncwarp();
            uint32_t ahi[4];
            ahi[0] = f2tf(sPw[g * 12 + t]);
            ahi[1] = f2tf(sPw[(g + 8) * 12 + t]);
            ahi[2] = f2tf(sPw[g * 12 + t + 4]);
            ahi[3] = f2tf(sPw[(g + 8) * 12 + t + 4]);
            __syncwarp();
            const int k0 = kt * 8;
#pragma unroll
            for (int nt = 0; nt < 16; nt++) {
                uint32_t b0 = sVu[(k0 + t) * VSTR + nt * 8 + g];
                uint32_t b1 = sVu[(k0 + t + 4) * VSTR + nt * 8 + g];
                mma_tf32(O[nt], ahi, b0, b1);
            }
        }
    }

    // ---- epilogue: normalize and store ----
    float inv0 = 1.0f / l_i[0];
    float inv1 = 1.0f / l_i[1];
    size_t row0 = (size_t)b * TT + q0 + mBase + g;
    size_t row1 = row0 + 8;
#pragma unroll
    for (int nt = 0; nt < 16; nt++) {
        int col = nt * 8 + 2 * t;
        *(float2*)&out[row0 * DD + col] = make_float2(O[nt][0] * inv0, O[nt][1] * inv0);
        *(float2*)&out[row1 * DD + col] = make_float2(O[nt][2] * inv1, O[nt][3] * inv1);
    }
}

// ---------------------------------------------------------------------------
extern "C" void kernel_launch(void* const* d_in, const int* in_sizes, int n_in,
                              void* d_out, int out_size) {
    const float* x = (const float*)d_in[0];   // [8, 4096, 1024] fp32
    const float* W = (const float*)d_in[1];   // [128, 1024] fp32
    float* out = (float*)d_out;               // [8, 4096, 128] fp32

    cudaFuncSetAttribute(attn_kernel, cudaFuncAttributeMaxDynamicSharedMemorySize,
                         ATT_SMEM);

    proj_rope_kernel<<<(BB * TT) / 64, 128>>>(x, W);
    attn_kernel<<<dim3(BB, 32), 256, ATT_SMEM>>>(out);
}

// round 16
// speedup vs baseline: 1.6273x; 1.6273x over previous
#include <cuda_runtime.h>
#include <math.h>
#include <stdint.h>

#define BB 8
#define TT 4096
#define NM 1024
#define DD 128

// Scratch: k_rot (acts as Q and K) and v (= k pre-RoPE)
__device__ float g_k[BB * TT * DD];
__device__ float g_v[BB * TT * DD];

__device__ __forceinline__ uint32_t f2tf(float x) {
    uint32_t r;
    asm("cvt.rna.tf32.f32 %0, %1;" : "=r"(r) : "f"(x));
    return r;
}

__device__ __forceinline__ void mma_tf32(float* c, const uint32_t* a,
                                         uint32_t b0, uint32_t b1) {
    asm volatile(
        "mma.sync.aligned.m16n8k8.row.col.f32.tf32.tf32.f32 "
        "{%0,%1,%2,%3}, {%4,%5,%6,%7}, {%8,%9}, {%0,%1,%2,%3};\n"
        : "+f"(c[0]), "+f"(c[1]), "+f"(c[2]), "+f"(c[3])
        : "r"(a[0]), "r"(a[1]), "r"(a[2]), "r"(a[3]), "r"(b0), "r"(b1));
}

// ---------------------------------------------------------------------------
// Kernel 1: k = x @ W_K^T via single-pass tf32 mma (x and W tf32-rounded),
// RoPE fused in the epilogue (C-fragment cols 2t,2t+1 are the RoPE pair).
// Error model: ~2e-4 rel on k; enters V linearly, K/Q contracted by softmax.
// ---------------------------------------------------------------------------
__global__ __launch_bounds__(128) void proj_rope_kernel(
    const float* __restrict__ x, const float* __restrict__ W) {
    __shared__ uint32_t sXu[64 * 36];
    __shared__ uint32_t sWu[128 * 36];

    const int tid = threadIdx.x;
    const int w = tid >> 5;
    const int lane = tid & 31;
    const int g = lane >> 2;
    const int t = lane & 3;
    const int mBase = w * 16;
    const int m0 = blockIdx.x * 64;

    float c[16][4];
#pragma unroll
    for (int nt = 0; nt < 16; nt++)
#pragma unroll
        for (int e = 0; e < 4; e++) c[nt][e] = 0.f;

    for (int kc = 0; kc < NM; kc += 32) {
        __syncthreads();
#pragma unroll
        for (int p = 0; p < 4; p++) {
            int idx = tid + 128 * p;
            int row = idx >> 3;
            int c4 = (idx & 7) * 4;
            float4 xv = *(const float4*)&x[(size_t)(m0 + row) * NM + kc + c4];
            uint4 xu = make_uint4(f2tf(xv.x), f2tf(xv.y), f2tf(xv.z), f2tf(xv.w));
            *(uint4*)&sXu[row * 36 + c4] = xu;
        }
#pragma unroll
        for (int p = 0; p < 8; p++) {
            int idx = tid + 128 * p;
            int row = idx >> 3;
            int c4 = (idx & 7) * 4;
            float4 wv = *(const float4*)&W[(size_t)row * NM + kc + c4];
            uint4 wu = make_uint4(f2tf(wv.x), f2tf(wv.y), f2tf(wv.z), f2tf(wv.w));
            *(uint4*)&sWu[row * 36 + c4] = wu;
        }
        __syncthreads();

#pragma unroll
        for (int kt = 0; kt < 4; kt++) {
            const int k0 = kt * 8;
            uint32_t ahi[4];
            ahi[0] = sXu[(mBase + g) * 36 + k0 + t];
            ahi[1] = sXu[(mBase + g + 8) * 36 + k0 + t];
            ahi[2] = sXu[(mBase + g) * 36 + k0 + t + 4];
            ahi[3] = sXu[(mBase + g + 8) * 36 + k0 + t + 4];
#pragma unroll
            for (int nt = 0; nt < 16; nt++) {
                uint32_t b0 = sWu[(nt * 8 + g) * 36 + k0 + t];
                uint32_t b1 = sWu[(nt * 8 + g) * 36 + k0 + t + 4];
                mma_tf32(c[nt], ahi, b0, b1);
            }
        }
    }

    const size_t row0 = (size_t)(m0 + mBase + g);
    const size_t row1 = row0 + 8;
#pragma unroll
    for (int nt = 0; nt < 16; nt++) {
        int col = nt * 8 + 2 * t;
        int h = col >> 1;
        float ang = powf(10000.0f, -(float)h * (1.0f / 64.0f));
        float cc = cosf(ang), ss = sinf(ang);
        float e0 = fmaf(c[nt][0], cc, c[nt][1] * ss);
        float o0 = fmaf(-e0, ss, c[nt][1] * cc);
        float e1 = fmaf(c[nt][2], cc, c[nt][3] * ss);
        float o1 = fmaf(-e1, ss, c[nt][3] * cc);
        *(float2*)&g_v[row0 * DD + col] = make_float2(c[nt][0], c[nt][1]);
        *(float2*)&g_v[row1 * DD + col] = make_float2(c[nt][2], c[nt][3]);
        *(float2*)&g_k[row0 * DD + col] = make_float2(e0, o0);
        *(float2*)&g_k[row1 * DD + col] = make_float2(e1, o1);
    }
}

// ---------------------------------------------------------------------------
// Kernel 2: causal flash attention, single-pass tf32 mma.
// BLOCK_M=64 (4 warps x 16 rows), BLOCK_N=64, 128 threads, 2 CTAs/SM.
// Q stored tf32-hi (pre-scaled) in smem ONCE; softmax contracts logit-side
// rounding, so no lo-pass anywhere. P hi-only in PV.
// smem: sQ[64][132] tf32 | sKu[64][132] | sVu[64][136] | sP 4x[16][12]
//       = 105472 B -> 2 CTAs/SM.
// ---------------------------------------------------------------------------
#define QSTR 132
#define KSTR 132
#define VSTR 136
#define OFF_K (64 * QSTR)
#define OFF_V (OFF_K + 64 * KSTR)
#define OFF_P (OFF_V + 64 * VSTR)
#define ATT_SMEM ((OFF_P + 4 * 16 * 12) * 4)

__global__ __launch_bounds__(128, 2) void attn_kernel(float* __restrict__ out) {
    extern __shared__ uint32_t smu[];
    uint32_t* sQ = smu;
    uint32_t* sKu = smu + OFF_K;
    uint32_t* sVu = smu + OFF_V;
    float* sP = (float*)(smu + OFF_P);

    const int tid = threadIdx.x;
    const int w = tid >> 5;
    const int lane = tid & 31;
    const int g = lane >> 2;
    const int t = lane & 3;
    const int mBase = w * 16;

    const int b = blockIdx.y;
    const int i_tile = 63 - (int)blockIdx.x;  // heavy tiles first
    const int q0 = i_tile * 64;

    const float* __restrict__ Kb = g_k + (size_t)b * TT * DD;
    const float* __restrict__ Vb = g_v + (size_t)b * TT * DD;
    float* sPw = sP + w * 16 * 12;

    const float SCALE = 0.08838834764831845f;  // 128^-0.5
    const float NEG_INF = __int_as_float(0xff800000);

    // ---- fill Q ONCE (pre-scaled, tf32 hi) ----
#pragma unroll
    for (int p = 0; p < 16; p++) {
        int idx = tid + 128 * p;          // 0..2047 float4 units
        int row = idx >> 5;
        int c4 = (idx & 31) * 4;
        float4 v = *(const float4*)&Kb[(size_t)(q0 + row) * DD + c4];
        uint4 hi = make_uint4(f2tf(v.x * SCALE), f2tf(v.y * SCALE),
                              f2tf(v.z * SCALE), f2tf(v.w * SCALE));
        *(uint4*)&sQ[row * QSTR + c4] = hi;
    }

    float O[16][4];
    float m_i[2], l_i[2];
#pragma unroll
    for (int nt = 0; nt < 16; nt++)
#pragma unroll
        for (int e = 0; e < 4; e++) O[nt][e] = 0.f;
    m_i[0] = NEG_INF; m_i[1] = NEG_INF;
    l_i[0] = 0.f; l_i[1] = 0.f;

    for (int jt = 0; jt <= i_tile; jt++) {
        const int j0 = jt * 64;
        __syncthreads();  // prior iter done with sK/sV; also orders Q fill

        // ---- fill K/V (tf32-rounded) ----
#pragma unroll
        for (int p = 0; p < 16; p++) {
            int idx = tid + 128 * p;      // 0..2047 float4 units
            int row = idx >> 5;
            int c4 = (idx & 31) * 4;
            float4 kv = *(const float4*)&Kb[(size_t)(j0 + row) * DD + c4];
            uint4 ku = make_uint4(f2tf(kv.x), f2tf(kv.y), f2tf(kv.z), f2tf(kv.w));
            *(uint4*)&sKu[row * KSTR + c4] = ku;
            float4 vv = *(const float4*)&Vb[(size_t)(j0 + row) * DD + c4];
            uint4 vu = make_uint4(f2tf(vv.x), f2tf(vv.y), f2tf(vv.z), f2tf(vv.w));
            *(uint4*)&sVu[row * VSTR + c4] = vu;
        }
        __syncthreads();

        // ---- S = Q K^T (single pass) ----
        float c[8][4];
#pragma unroll
        for (int nt = 0; nt < 8; nt++)
#pragma unroll
            for (int e = 0; e < 4; e++) c[nt][e] = 0.f;

#pragma unroll 8
        for (int kt = 0; kt < 16; kt++) {
            const int k0 = kt * 8;
            uint32_t ahi[4];
            ahi[0] = sQ[(mBase + g) * QSTR + k0 + t];
            ahi[1] = sQ[(mBase + g + 8) * QSTR + k0 + t];
            ahi[2] = sQ[(mBase + g) * QSTR + k0 + t + 4];
            ahi[3] = sQ[(mBase + g + 8) * QSTR + k0 + t + 4];
#pragma unroll
            for (int nt = 0; nt < 8; nt++) {
                uint32_t b0 = sKu[(nt * 8 + g) * KSTR + k0 + t];
                uint32_t b1 = sKu[(nt * 8 + g) * KSTR + k0 + t + 4];
                mma_tf32(c[nt], ahi, b0, b1);
            }
        }

        // ---- causal mask on the diagonal tile ----
        if (jt == i_tile) {
            const int r0 = mBase + g;
            const int r1 = mBase + g + 8;
#pragma unroll
            for (int nt = 0; nt < 8; nt++) {
                int c0 = nt * 8 + 2 * t;
                if (c0 > r0) c[nt][0] = NEG_INF;
                if (c0 + 1 > r0) c[nt][1] = NEG_INF;
                if (c0 > r1) c[nt][2] = NEG_INF;
                if (c0 + 1 > r1) c[nt][3] = NEG_INF;
            }
        }

        // ---- online softmax (rows g and g+8) ----
#pragma unroll
        for (int ri = 0; ri < 2; ri++) {
            float mx = NEG_INF;
#pragma unroll
            for (int nt = 0; nt < 8; nt++)
                mx = fmaxf(mx, fmaxf(c[nt][2 * ri], c[nt][2 * ri + 1]));
            mx = fmaxf(mx, __shfl_xor_sync(0xffffffffu, mx, 1));
            mx = fmaxf(mx, __shfl_xor_sync(0xffffffffu, mx, 2));
            float mnew = fmaxf(m_i[ri], mx);
            float sc = __expf(m_i[ri] - mnew);
            float rsum = 0.f;
#pragma unroll
            for (int nt = 0; nt < 8; nt++) {
                c[nt][2 * ri] = __expf(c[nt][2 * ri] - mnew);
                c[nt][2 * ri + 1] = __expf(c[nt][2 * ri + 1] - mnew);
                rsum += c[nt][2 * ri] + c[nt][2 * ri + 1];
            }
            rsum += __shfl_xor_sync(0xffffffffu, rsum, 1);
            rsum += __shfl_xor_sync(0xffffffffu, rsum, 2);
            l_i[ri] = l_i[ri] * sc + rsum;
            m_i[ri] = mnew;
#pragma unroll
            for (int nt = 0; nt < 16; nt++) {
                O[nt][2 * ri] *= sc;
                O[nt][2 * ri + 1] *= sc;
            }
        }

        // ---- O += P V (P hi-only; P in [0,1]) ----
#pragma unroll
        for (int kt = 0; kt < 8; kt++) {
            *(float2*)&sPw[g * 12 + 2 * t] = make_float2(c[kt][0], c[kt][1]);
            *(float2*)&sPw[(g + 8) * 12 + 2 * t] = make_float2(c[kt][2], c[kt][3]);
            __syncwarp();
            uint32_t ahi[4];
            ahi[0] = f2tf(sPw[g * 12 + t]);
            ahi[1] = f2tf(sPw[(g + 8) * 12 + t]);
            ahi[2] = f2tf(sPw[g * 12 + t + 4]);
            ahi[3] = f2tf(sPw[(g + 8) * 12 + t + 4]);
            __syncwarp();
            const int k0 = kt * 8;
#pragma unroll
            for (int nt = 0; nt < 16; nt++) {
                uint32_t b0 = sVu[(k0 + t) * VSTR + nt * 8 + g];
                uint32_t b1 = sVu[(k0 + t + 4) * VSTR + nt * 8 + g];
                mma_tf32(O[nt], ahi, b0, b1);
            }
        }
    }

    // ---- epilogue: normalize and store ----
    float inv0 = 1.0f / l_i[0];
    float inv1 = 1.0f / l_i[1];
    size_t row0 = (size_t)b * TT + q0 + mBase + g;
    size_t row1 = row0 + 8;
#pragma unroll
    for (int nt = 0; nt < 16; nt++) {
        int col = nt * 8 + 2 * t;
        *(float2*)&out[row0 * DD + col] = make_float2(O[nt][0] * inv0, O[nt][1] * inv0);
        *(float2*)&out[row1 * DD + col] = make_float2(O[nt][2] * inv1, O[nt][3] * inv1);
    }
}

// ---------------------------------------------------------------------------
extern "C" void kernel_launch(void* const* d_in, const int* in_sizes, int n_in,
                              void* d_out, int out_size) {
    const float* x = (const float*)d_in[0];   // [8, 4096, 1024] fp32
    const float* W = (const float*)d_in[1];   // [128, 1024] fp32
    float* out = (float*)d_out;               // [8, 4096, 128] fp32

    cudaFuncSetAttribute(attn_kernel, cudaFuncAttributeMaxDynamicSharedMemorySize,
                         ATT_SMEM);

    proj_rope_kernel<<<(BB * TT) / 64, 128>>>(x, W);
    attn_kernel<<<dim3(64, BB), 128, ATT_SMEM>>>(out);
}